// round 6
// baseline (speedup 1.0000x reference)
#include <cuda_runtime.h>

#define N_NODES 100000
#define N_EDGES 600000
#define F_IN 128
#define F_OUT 64
#define TM 256
#define BK 16
#define AS_PITCH (TM + 4)   // 260 floats: 1040B row stride, 16B-aligned

// Scratch (no allocation allowed in kernel_launch)
__device__ float s_xp[(size_t)N_NODES * F_OUT];
__device__ float s_deg[N_NODES];   // zero-initialized; k_dis re-zeroes after use
__device__ float s_dis[N_NODES];
__device__ float s_inv_sigma;

// ---------------------------------------------------------------------------
// packed fp32x2 helpers (sm_100+: fma.rn.f32x2)
// ---------------------------------------------------------------------------
__device__ __forceinline__ unsigned long long pack2(float lo, float hi) {
    unsigned long long r;
    asm("mov.b64 %0, {%1, %2};" : "=l"(r) : "f"(lo), "f"(hi));
    return r;
}
__device__ __forceinline__ void unpack2(unsigned long long v, float& lo, float& hi) {
    asm("mov.b64 {%0, %1}, %2;" : "=f"(lo), "=f"(hi) : "l"(v));
}
__device__ __forceinline__ void ffma2(unsigned long long& d,
                                      unsigned long long a,
                                      unsigned long long b) {
    asm("fma.rn.f32x2 %0, %1, %2, %0;" : "+l"(d) : "l"(a), "l"(b));
}

// ---------------------------------------------------------------------------
// sigma = ||W (W^T u / ||W^T u||)||  ->  store 1/sigma
// ---------------------------------------------------------------------------
__global__ void k_sigma(const float* __restrict__ W, const float* __restrict__ u) {
    __shared__ float v[F_OUT];
    __shared__ float red[128];
    __shared__ float n1_s;
    int t = threadIdx.x;

    if (t < F_OUT) {
        float s = 0.f;
        for (int i = 0; i < F_IN; i++) s += W[i * F_OUT + t] * u[i];
        v[t] = s;
    }
    __syncthreads();

    red[t] = (t < F_OUT) ? v[t] * v[t] : 0.f;
    __syncthreads();
    for (int s = 64; s > 0; s >>= 1) {
        if (t < s) red[t] += red[t + s];
        __syncthreads();
    }
    if (t == 0) n1_s = sqrtf(red[0]);
    __syncthreads();

    float g = 0.f;
    for (int j = 0; j < F_OUT; j++) g += W[t * F_OUT + j] * v[j];
    red[t] = g * g;
    __syncthreads();
    for (int s = 64; s > 0; s >>= 1) {
        if (t < s) red[t] += red[t + s];
        __syncthreads();
    }
    if (t == 0) {
        float n2 = sqrtf(red[0]);
        s_inv_sigma = n1_s / n2;   // 1/sigma = ||v_raw|| / ||W v_raw||
    }
}

// ---------------------------------------------------------------------------
// deg accumulation (deg starts at 0 each replay; self-loop +1 folded in k_dis)
// ---------------------------------------------------------------------------
__global__ void k_deg_acc(const int* __restrict__ ei,
                          const float* __restrict__ ew) {
    int e = blockIdx.x * blockDim.x + threadIdx.x;
    if (e < N_EDGES) {
        int col = ei[N_EDGES + e];
        float w = 1.f / (1.f + __expf(-ew[e]));
        atomicAdd(&s_deg[col], w);
    }
}

// dis = rsqrt(deg + 1), then reset deg to 0 for the next graph replay
__global__ void k_dis() {
    int i = blockIdx.x * blockDim.x + threadIdx.x;
    if (i < N_NODES) {
        float d = s_deg[i] + 1.0f;
        s_dis[i] = rsqrtf(d);
        s_deg[i] = 0.0f;
    }
}

// ---------------------------------------------------------------------------
// xp = x @ (W/sigma); out = xp/deg + bias (self-loop); stash xp in L2.
// 256 rows x 64 cols per block, 256 threads, 8x8 per-thread register tile.
// Mainloop: f32x2 row-pair accumulators (A pairs come straight off LDS).
// ---------------------------------------------------------------------------
__global__ __launch_bounds__(256, 2) void k_gemm(const float* __restrict__ x,
                                                 const float* __restrict__ W,
                                                 const float* __restrict__ bias,
                                                 float* __restrict__ out) {
    __shared__ float Ws[F_IN][F_OUT];        // 32 KB (scaled by 1/sigma)
    __shared__ float As[BK][AS_PITCH];       // 16.6 KB, transposed A chunk

    int tid = threadIdx.x;
    int tx = tid & 7;       // col group: 8 cols each
    int ty = tid >> 3;      // row group: 8 rows each (0..31)
    int r0 = blockIdx.x * TM;

    float inv_sigma = s_inv_sigma;
    for (int i = tid; i < F_IN * F_OUT; i += 256)
        (&Ws[0][0])[i] = W[i] * inv_sigma;

    unsigned long long accp[4][8];   // [row pair][col] f32x2 over (2r, 2r+1)
    #pragma unroll
    for (int i = 0; i < 4; i++)
        #pragma unroll
        for (int j = 0; j < 8; j++) accp[i][j] = 0ull;

    for (int kc = 0; kc < F_IN; kc += BK) {
        __syncthreads();
        #pragma unroll
        for (int l = 0; l < 4; l++) {
            int idx = tid + l * 256;        // 0..1023 float4 slots
            int row = idx >> 2;             // 0..255
            int kq  = idx & 3;              // float4 within k-chunk
            int grow = r0 + row;
            float4 val = make_float4(0.f, 0.f, 0.f, 0.f);
            if (grow < N_NODES)
                val = *(const float4*)&x[(size_t)grow * F_IN + kc + kq * 4];
            As[kq * 4 + 0][row] = val.x;
            As[kq * 4 + 1][row] = val.y;
            As[kq * 4 + 2][row] = val.z;
            As[kq * 4 + 3][row] = val.w;
        }
        __syncthreads();

        #pragma unroll
        for (int k = 0; k < BK; k++) {
            // A: 8 rows as 4 natural f32x2 pairs (two LDS.128)
            ulonglong2 a01 = *(const ulonglong2*)&As[k][ty * 8];
            ulonglong2 a23 = *(const ulonglong2*)&As[k][ty * 8 + 4];
            // B: 8 cols (two LDS.128)
            float4 b0 = *(const float4*)&Ws[kc + k][tx * 8];
            float4 b1 = *(const float4*)&Ws[kc + k][tx * 8 + 4];
            float bv[8] = {b0.x, b0.y, b0.z, b0.w, b1.x, b1.y, b1.z, b1.w};
            #pragma unroll
            for (int c = 0; c < 8; c++) {
                unsigned long long bd = pack2(bv[c], bv[c]);
                ffma2(accp[0][c], a01.x, bd);
                ffma2(accp[1][c], a01.y, bd);
                ffma2(accp[2][c], a23.x, bd);
                ffma2(accp[3][c], a23.y, bd);
            }
        }
    }

    float4 bb0 = *(const float4*)&bias[tx * 8];
    float4 bb1 = *(const float4*)&bias[tx * 8 + 4];
    float bv[8] = {bb0.x, bb0.y, bb0.z, bb0.w, bb1.x, bb1.y, bb1.z, bb1.w};

    #pragma unroll
    for (int i = 0; i < 8; i++) {
        int row = r0 + ty * 8 + i;
        if (row < N_NODES) {
            int rp = i >> 1, hi = i & 1;
            float vals[8];
            #pragma unroll
            for (int c = 0; c < 8; c++) {
                float lo, hh;
                unpack2(accp[rp][c], lo, hh);
                vals[c] = hi ? hh : lo;
            }
            float d = s_dis[row];
            float inv_deg = d * d;
            float4 xp0 = make_float4(vals[0], vals[1], vals[2], vals[3]);
            float4 xp1 = make_float4(vals[4], vals[5], vals[6], vals[7]);
            *(float4*)&s_xp[(size_t)row * F_OUT + tx * 8]     = xp0;
            *(float4*)&s_xp[(size_t)row * F_OUT + tx * 8 + 4] = xp1;
            float4 o0 = make_float4(vals[0] * inv_deg + bv[0], vals[1] * inv_deg + bv[1],
                                    vals[2] * inv_deg + bv[2], vals[3] * inv_deg + bv[3]);
            float4 o1 = make_float4(vals[4] * inv_deg + bv[4], vals[5] * inv_deg + bv[5],
                                    vals[6] * inv_deg + bv[6], vals[7] * inv_deg + bv[7]);
            *(float4*)&out[(size_t)row * F_OUT + tx * 8]     = o0;
            *(float4*)&out[(size_t)row * F_OUT + tx * 8 + 4] = o1;
        }
    }
}

// ---------------------------------------------------------------------------
// Edge aggregation: out[col] += dis[row]*sigmoid(ew)*dis[col] * xp[row]
// 4 edges per warp: 16 lanes/edge, 2 edges sequentially per lane group
// (independent gathers issued together for MLP=2), float4 RED scatter.
// ---------------------------------------------------------------------------
__global__ __launch_bounds__(256) void k_edge(const int* __restrict__ ei,
                                              const float* __restrict__ ew,
                                              float* __restrict__ out) {
    int gtid = blockIdx.x * blockDim.x + threadIdx.x;
    int lane = threadIdx.x & 31;
    int half = lane >> 4;       // edge subgroup within warp
    int sub  = lane & 15;       // float4 slot within edge
    int ebase = (gtid >> 5) * 4 + half * 2;   // warp covers 4 edges

    int   rowv[2], colv[2];
    float cf[2];
    #pragma unroll
    for (int j = 0; j < 2; j++) {
        int e = ebase + j;
        rowv[j] = ei[e];
        colv[j] = ei[N_EDGES + e];
        float w = 1.f / (1.f + __expf(-ew[e]));
        cf[j] = s_dis[rowv[j]] * w * s_dis[colv[j]];
    }

    float4 xv0 = *(const float4*)&s_xp[(size_t)rowv[0] * F_OUT + sub * 4];
    float4 xv1 = *(const float4*)&s_xp[(size_t)rowv[1] * F_OUT + sub * 4];

    float4 m0 = make_float4(xv0.x * cf[0], xv0.y * cf[0], xv0.z * cf[0], xv0.w * cf[0]);
    atomicAdd((float4*)&out[(size_t)colv[0] * F_OUT + sub * 4], m0);
    float4 m1 = make_float4(xv1.x * cf[1], xv1.y * cf[1], xv1.z * cf[1], xv1.w * cf[1]);
    atomicAdd((float4*)&out[(size_t)colv[1] * F_OUT + sub * 4], m1);
}

// ---------------------------------------------------------------------------
extern "C" void kernel_launch(void* const* d_in, const int* in_sizes, int n_in,
                              void* d_out, int out_size) {
    const float* x    = (const float*)d_in[0];
    const int*   ei   = (const int*)d_in[1];    // edge_index is int32 (JAX x64 off)
    const float* W    = (const float*)d_in[2];
    const float* bias = (const float*)d_in[3];
    const float* ew   = (const float*)d_in[4];
    const float* u    = (const float*)d_in[5];
    float* out = (float*)d_out;

    k_sigma<<<1, 128>>>(W, u);
    k_deg_acc<<<(N_EDGES + 255) / 256, 256>>>(ei, ew);
    k_dis<<<(N_NODES + 255) / 256, 256>>>();
    k_gemm<<<(N_NODES + TM - 1) / TM, 256>>>(x, W, bias, out);
    // 4 edges per warp: 600000/4 = 150000 warps / 8 per block = 18750 blocks
    k_edge<<<18750, 256>>>(ei, ew, out);
}